// round 4
// baseline (speedup 1.0000x reference)
#include <cuda_runtime.h>
#include <math.h>

#define BB 2
#define SS 2048
#define DD 1024
#define HH 16
#define HDIM 64
#define NEGV (-10000.0f)

// Scratch: projected Q/K/V in head-major [B,H,S,HD] and context in [B,S,D].
__device__ float g_Q[BB * HH * SS * HDIM];
__device__ float g_K[BB * HH * SS * HDIM];
__device__ float g_V[BB * HH * SS * HDIM];
__device__ float g_ctx[BB * SS * DD];

// ---------------------------------------------------------------------------
// Projection GEMM: out[m][n] = sum_k X[m][k] * W[n][k]   (X row-major MxK,
// W row-major NxK -> "NT" inner-product gemm). M=4096, N=1024, K=1024.
// Tiles: BM=128, BN=64, BK=16. 256 threads, 8x4 microtile per thread.
// blockIdx.z selects which of q/k/v; output written head-major into scratch.
// ---------------------------------------------------------------------------
__global__ __launch_bounds__(256, 4)
void proj_qkv_kernel(const float* __restrict__ q,
                     const float* __restrict__ k,
                     const float* __restrict__ v,
                     const float* __restrict__ Wq,
                     const float* __restrict__ Wk,
                     const float* __restrict__ Wv)
{
    const int which = blockIdx.z;
    const float* X = (which == 0) ? q : (which == 1) ? k : v;
    const float* W = (which == 0) ? Wq : (which == 1) ? Wk : Wv;
    float* O = (which == 0) ? g_Q : (which == 1) ? g_K : g_V;

    __shared__ float As[128][17];
    __shared__ float Bs[64][17];

    const int tid = threadIdx.x;
    const int tx = tid & 15;
    const int ty = tid >> 4;
    const int m0 = blockIdx.y * 128;
    const int n0 = blockIdx.x * 64;
    const int h = n0 >> 6;   // BN=64 == one head exactly

    float acc[8][4];
#pragma unroll
    for (int i = 0; i < 8; i++)
#pragma unroll
        for (int j = 0; j < 4; j++) acc[i][j] = 0.0f;

    for (int k0 = 0; k0 < 1024; k0 += 16) {
        // A tile: 128x16 = 2048 floats, 2 float4 per thread
#pragma unroll
        for (int it = 0; it < 2; it++) {
            int idx = tid * 4 + it * 1024;
            int r = idx >> 4, kk = idx & 15;
            float4 a4 = *(const float4*)&X[(size_t)(m0 + r) * 1024 + k0 + kk];
            As[r][kk + 0] = a4.x; As[r][kk + 1] = a4.y;
            As[r][kk + 2] = a4.z; As[r][kk + 3] = a4.w;
        }
        // B tile: 64x16 = 1024 floats, 1 float4 per thread
        {
            int idx = tid * 4;
            int r = idx >> 4, kk = idx & 15;
            float4 b4 = *(const float4*)&W[(size_t)(n0 + r) * 1024 + k0 + kk];
            Bs[r][kk + 0] = b4.x; Bs[r][kk + 1] = b4.y;
            Bs[r][kk + 2] = b4.z; Bs[r][kk + 3] = b4.w;
        }
        __syncthreads();

#pragma unroll
        for (int kk = 0; kk < 16; kk++) {
            float a[8], b[4];
#pragma unroll
            for (int i = 0; i < 8; i++) a[i] = As[ty * 8 + i][kk];
#pragma unroll
            for (int j = 0; j < 4; j++) b[j] = Bs[tx * 4 + j][kk];
#pragma unroll
            for (int i = 0; i < 8; i++)
#pragma unroll
                for (int j = 0; j < 4; j++) acc[i][j] = fmaf(a[i], b[j], acc[i][j]);
        }
        __syncthreads();
    }

    // Write head-major: O[((b*H + h)*S + s)*HD + hd]
#pragma unroll
    for (int i = 0; i < 8; i++) {
        int m = m0 + ty * 8 + i;
        int bidx = m >> 11;          // m / 2048
        int s = m & 2047;
        float4 o4 = make_float4(acc[i][0], acc[i][1], acc[i][2], acc[i][3]);
        *(float4*)&O[((size_t)(bidx * HH + h) * SS + s) * HDIM + tx * 4] = o4;
    }
}

// ---------------------------------------------------------------------------
// Flash attention (fp32, online softmax). One CTA = 64 query rows of one
// (b,h). Iterates ALL 64 column tiles of 32 (exact reference semantics incl.
// rows whose entire visible prefix is padded). 256 threads.
// Static smem only (~42 KB) -> no cudaFuncSetAttribute needed.
// ---------------------------------------------------------------------------
__global__ __launch_bounds__(256, 2)
void flash_attn_kernel(const int* __restrict__ attn_mask,
                       const int* __restrict__ mask_future)
{
    __shared__ float Qs[64][65];
    __shared__ float Ks[32][65];
    __shared__ float Vs[32][65];
    __shared__ float Ps[64][33];
    __shared__ int msk[32];

    const int tid = threadIdx.x;
    const int tx = tid & 15;
    const int ty = tid >> 4;
    const int row0 = blockIdx.x * 64;
    const int h = blockIdx.y;
    const int b = blockIdx.z;

    const float* Qp = &g_Q[(size_t)(b * HH + h) * SS * HDIM];
    const float* Kp = &g_K[(size_t)(b * HH + h) * SS * HDIM];
    const float* Vp = &g_V[(size_t)(b * HH + h) * SS * HDIM];

    const int mf = mask_future[0];
    const float scale = 0.125f;   // 1/sqrt(64)

    // Load Q tile (64x64): 16 floats per thread
#pragma unroll
    for (int it = 0; it < 4; it++) {
        int idx = tid * 4 + it * 1024;
        int r = idx >> 6, kk = idx & 63;
        float4 q4 = *(const float4*)&Qp[(size_t)(row0 + r) * HDIM + kk];
        Qs[r][kk + 0] = q4.x; Qs[r][kk + 1] = q4.y;
        Qs[r][kk + 2] = q4.z; Qs[r][kk + 3] = q4.w;
    }

    float m_i[4], l_i[4], Oacc[4][4];
#pragma unroll
    for (int i = 0; i < 4; i++) {
        m_i[i] = -INFINITY;
        l_i[i] = 0.0f;
#pragma unroll
        for (int j = 0; j < 4; j++) Oacc[i][j] = 0.0f;
    }
    __syncthreads();

    for (int c0 = 0; c0 < SS; c0 += 32) {
        // Load K and V tiles (32x64 each) + padding mask
#pragma unroll
        for (int it = 0; it < 2; it++) {
            int idx = tid * 4 + it * 1024;
            int r = idx >> 6, kk = idx & 63;
            float4 k4 = *(const float4*)&Kp[(size_t)(c0 + r) * HDIM + kk];
            Ks[r][kk + 0] = k4.x; Ks[r][kk + 1] = k4.y;
            Ks[r][kk + 2] = k4.z; Ks[r][kk + 3] = k4.w;
            float4 v4 = *(const float4*)&Vp[(size_t)(c0 + r) * HDIM + kk];
            Vs[r][kk + 0] = v4.x; Vs[r][kk + 1] = v4.y;
            Vs[r][kk + 2] = v4.z; Vs[r][kk + 3] = v4.w;
        }
        if (tid < 32) msk[tid] = attn_mask[b * SS + c0 + tid];
        __syncthreads();

        // S = Q K^T  (4 rows x 2 cols per thread)
        float sacc[4][2];
#pragma unroll
        for (int i = 0; i < 4; i++)
#pragma unroll
            for (int j = 0; j < 2; j++) sacc[i][j] = 0.0f;
#pragma unroll
        for (int kk = 0; kk < 64; kk++) {
            float a[4], bb[2];
#pragma unroll
            for (int i = 0; i < 4; i++) a[i] = Qs[ty * 4 + i][kk];
#pragma unroll
            for (int j = 0; j < 2; j++) bb[j] = Ks[tx * 2 + j][kk];
#pragma unroll
            for (int i = 0; i < 4; i++)
#pragma unroll
                for (int j = 0; j < 2; j++) sacc[i][j] = fmaf(a[i], bb[j], sacc[i][j]);
        }

        // Masks (pad overrides causal, matching reference order)
        int mvals[2];
#pragma unroll
        for (int j = 0; j < 2; j++) mvals[j] = msk[tx * 2 + j];

#pragma unroll
        for (int i = 0; i < 4; i++) {
            int row = row0 + ty * 4 + i;
            float tmax = -INFINITY;
#pragma unroll
            for (int j = 0; j < 2; j++) {
                int col = c0 + tx * 2 + j;
                float s = sacc[i][j] * scale;
                if (mf && col > row) s += NEGV;
                if (mvals[j] == 0) s = NEGV;
                sacc[i][j] = s;
                tmax = fmaxf(tmax, s);
            }
            // max across the 16 lanes sharing these rows (same ty)
#pragma unroll
            for (int off = 8; off >= 1; off >>= 1)
                tmax = fmaxf(tmax, __shfl_xor_sync(0xffffffffu, tmax, off));

            float mnew = fmaxf(m_i[i], tmax);
            float alpha = __expf(m_i[i] - mnew);
            float psum = 0.0f;
#pragma unroll
            for (int j = 0; j < 2; j++) {
                float p = __expf(sacc[i][j] - mnew);
                Ps[ty * 4 + i][tx * 2 + j] = p;
                psum += p;
            }
#pragma unroll
            for (int off = 8; off >= 1; off >>= 1)
                psum += __shfl_xor_sync(0xffffffffu, psum, off);

            l_i[i] = l_i[i] * alpha + psum;
            m_i[i] = mnew;
#pragma unroll
            for (int j = 0; j < 4; j++) Oacc[i][j] *= alpha;
        }
        __syncthreads();

        // O += P @ V  (4 rows x 4 cols per thread, sum over 32)
#pragma unroll
        for (int c = 0; c < 32; c++) {
            float a[4], bv[4];
#pragma unroll
            for (int i = 0; i < 4; i++) a[i] = Ps[ty * 4 + i][c];
#pragma unroll
            for (int j = 0; j < 4; j++) bv[j] = Vs[c][tx * 4 + j];
#pragma unroll
            for (int i = 0; i < 4; i++)
#pragma unroll
                for (int j = 0; j < 4; j++) Oacc[i][j] = fmaf(a[i], bv[j], Oacc[i][j]);
        }
        __syncthreads();
    }

    // Epilogue: normalize, write ctx[b][s][h*64+hd] (row-major [B,S,D])
#pragma unroll
    for (int i = 0; i < 4; i++) {
        float inv = 1.0f / l_i[i];
        int s = row0 + ty * 4 + i;
        float4 o4 = make_float4(Oacc[i][0] * inv, Oacc[i][1] * inv,
                                Oacc[i][2] * inv, Oacc[i][3] * inv);
        *(float4*)&g_ctx[((size_t)b * SS + s) * DD + h * 64 + tx * 4] = o4;
    }
}

// ---------------------------------------------------------------------------
// Output projection: out[m][n] = sum_k ctx[m][k] * Wo[n][k]
// Same tiling as proj_qkv. Writes d_out row-major [B,S,D].
// ---------------------------------------------------------------------------
__global__ __launch_bounds__(256, 4)
void out_proj_kernel(const float* __restrict__ Wo, float* __restrict__ out)
{
    __shared__ float As[128][17];
    __shared__ float Bs[64][17];

    const int tid = threadIdx.x;
    const int tx = tid & 15;
    const int ty = tid >> 4;
    const int m0 = blockIdx.y * 128;
    const int n0 = blockIdx.x * 64;
    const float* X = g_ctx;

    float acc[8][4];
#pragma unroll
    for (int i = 0; i < 8; i++)
#pragma unroll
        for (int j = 0; j < 4; j++) acc[i][j] = 0.0f;

    for (int k0 = 0; k0 < 1024; k0 += 16) {
#pragma unroll
        for (int it = 0; it < 2; it++) {
            int idx = tid * 4 + it * 1024;
            int r = idx >> 4, kk = idx & 15;
            float4 a4 = *(const float4*)&X[(size_t)(m0 + r) * 1024 + k0 + kk];
            As[r][kk + 0] = a4.x; As[r][kk + 1] = a4.y;
            As[r][kk + 2] = a4.z; As[r][kk + 3] = a4.w;
        }
        {
            int idx = tid * 4;
            int r = idx >> 4, kk = idx & 15;
            float4 b4 = *(const float4*)&Wo[(size_t)(n0 + r) * 1024 + k0 + kk];
            Bs[r][kk + 0] = b4.x; Bs[r][kk + 1] = b4.y;
            Bs[r][kk + 2] = b4.z; Bs[r][kk + 3] = b4.w;
        }
        __syncthreads();

#pragma unroll
        for (int kk = 0; kk < 16; kk++) {
            float a[8], b[4];
#pragma unroll
            for (int i = 0; i < 8; i++) a[i] = As[ty * 8 + i][kk];
#pragma unroll
            for (int j = 0; j < 4; j++) b[j] = Bs[tx * 4 + j][kk];
#pragma unroll
            for (int i = 0; i < 8; i++)
#pragma unroll
                for (int j = 0; j < 4; j++) acc[i][j] = fmaf(a[i], b[j], acc[i][j]);
        }
        __syncthreads();
    }

#pragma unroll
    for (int i = 0; i < 8; i++) {
        int m = m0 + ty * 8 + i;
        float4 o4 = make_float4(acc[i][0], acc[i][1], acc[i][2], acc[i][3]);
        *(float4*)&out[(size_t)m * 1024 + n0 + tx * 4] = o4;
    }
}

// ---------------------------------------------------------------------------
// Launch. Inputs (metadata order): q, k, v, attn_mask, Wq, Wk, Wv, Wo,
// mask_future. Output: [B,S,D] float32.
// ---------------------------------------------------------------------------
extern "C" void kernel_launch(void* const* d_in, const int* in_sizes, int n_in,
                              void* d_out, int out_size)
{
    const float* q  = (const float*)d_in[0];
    const float* k  = (const float*)d_in[1];
    const float* v  = (const float*)d_in[2];
    const int* attn_mask = (const int*)d_in[3];
    const float* Wq = (const float*)d_in[4];
    const float* Wk = (const float*)d_in[5];
    const float* Wv = (const float*)d_in[6];
    const float* Wo = (const float*)d_in[7];
    const int* mask_future = (const int*)d_in[8];
    float* out = (float*)d_out;

    // 1. Q/K/V projections (z selects tensor)
    {
        dim3 grid(DD / 64, (BB * SS) / 128, 3);
        proj_qkv_kernel<<<grid, 256>>>(q, k, v, Wq, Wk, Wv);
    }
    // 2. Flash attention
    {
        dim3 grid(SS / 64, HH, BB);
        flash_attn_kernel<<<grid, 256>>>(attn_mask, mask_future);
    }
    // 3. Output projection
    {
        dim3 grid(DD / 64, (BB * SS) / 128);
        out_proj_kernel<<<grid, 256>>>(Wo, out);
    }
}